// round 7
// baseline (speedup 1.0000x reference)
#include <cuda_runtime.h>

typedef unsigned long long u64;
typedef unsigned int u32;

#define HW (512*512)

// ---------------- device scratch ----------------
// Max table: 240 pairs (eh>=1 lights only; the 32 identical eh=0 lights are
// handled analytically):  g_mtab_a[j*4]={hx0,hx1,hy0,hy1}, g_mtab_z[j*2]={hz0,hz1}
__device__ __align__(16) float g_mtab_a[240 * 4];
__device__ __align__(16) float g_mtab_z[240 * 2];
// Shade table: per batch, 240 pairs * 12 floats (3 float4):
//   [hx0,hx1,hy0,hy1][hz0,hz1,wr0,wr1][wg0,wg1,wb0,wb1],  w = env*sin(phi)/60
__device__ __align__(16) float g_stab[2 * 240 * 12];
__device__ u32 g_maxbits;
__device__ u32 g_ctr_max;
__device__ u32 g_ctr_shade;

// ---------------- packed f32x2 helpers ----------------
__device__ __forceinline__ u64 pk2(float lo, float hi) {
    u64 r;
    asm("mov.b64 %0, {%1, %2};" : "=l"(r) : "r"(__float_as_uint(lo)), "r"(__float_as_uint(hi)));
    return r;
}
__device__ __forceinline__ void unpk2(u64 v, float& lo, float& hi) {
    u32 a, b;
    asm("mov.b64 {%0, %1}, %2;" : "=r"(a), "=r"(b) : "l"(v));
    lo = __uint_as_float(a); hi = __uint_as_float(b);
}
__device__ __forceinline__ u64 dup2(float x) { return pk2(x, x); }
__device__ __forceinline__ u64 fma2_(u64 a, u64 b, u64 c) {
    u64 d; asm("fma.rn.f32x2 %0, %1, %2, %3;" : "=l"(d) : "l"(a), "l"(b), "l"(c)); return d;
}
__device__ __forceinline__ u64 mul2_(u64 a, u64 b) {
    u64 d; asm("mul.rn.f32x2 %0, %1, %2;" : "=l"(d) : "l"(a), "l"(b)); return d;
}
// packed relu: bits(relu(x)) == max_s32(bits(x), 0)
__device__ __forceinline__ u64 relu2(u64 s) {
    u32 lo, hi;
    asm("mov.b64 {%0,%1}, %2;" : "=r"(lo), "=r"(hi) : "l"(s));
    asm("max.s32 %0, %0, 0;" : "+r"(lo));
    asm("max.s32 %0, %0, 0;" : "+r"(hi));
    u64 r;
    asm("mov.b64 %0, {%1,%2};" : "=l"(r) : "r"(lo), "r"(hi));
    return r;
}
// packed running-max (halves of m >= 0, so s32 max == float max)
__device__ __forceinline__ u64 max2_s32(u64 m, u64 s) {
    u32 ml, mh, sl, sh;
    asm("mov.b64 {%0,%1}, %2;" : "=r"(ml), "=r"(mh) : "l"(m));
    asm("mov.b64 {%0,%1}, %2;" : "=r"(sl), "=r"(sh) : "l"(s));
    asm("max.s32 %0, %0, %1;" : "+r"(ml) : "r"(sl));
    asm("max.s32 %0, %0, %1;" : "+r"(mh) : "r"(sh));
    u64 r;
    asm("mov.b64 %0, {%1,%2};" : "=l"(r) : "r"(ml), "r"(mh));
    return r;
}

// ---------------- kernel 0: constants + tables + counter reset ----------------
__global__ void k_setup(const float* __restrict__ env) {
    int m = threadIdx.x;              // 0..511
    if (m == 0) { g_maxbits = 0u; g_ctr_max = 0u; g_ctr_shade = 0u; }

    int eh = m >> 5, ew = m & 31;
    const float PI_F = 3.14159274101257324e+00f;
    float phi = ((float)eh * (1.0f / 16.0f)) * PI_F;
    float th  = (((float)ew * (1.0f / 32.0f)) * 2.0f) * PI_F;

    float sp = sinf(phi), cp = cosf(phi);
    float st = sinf(th),  ct = cosf(th);

    // l = (st*sp, cp, -ct*sp); v = (0,0,1); h = normalize(v + l)
    float hx = st * sp;
    float hy = cp;
    float hz = 1.0f - ct * sp;
    float nrm = sqrtf(hx * hx + hy * hy + hz * hz);
    float rin = 1.0f / nrm;
    hx *= rin; hy *= rin; hz *= rin;

    if (m >= 32) {                    // 480 lights -> 240 pairs
        int i = m - 32, j = i >> 1, half = i & 1;

        // max table (h only)
        g_mtab_a[j * 4 + 0 + half] = hx;
        g_mtab_a[j * 4 + 2 + half] = hy;
        g_mtab_z[j * 2 + half]     = hz;

        // shade table
        const float SC = (float)(1.0 / 60.0);
        float sw = sp * SC;
        #pragma unroll
        for (int b = 0; b < 2; ++b) {
            float* row = g_stab + (b * 240 + j) * 12;
            row[0 + half]  = hx;
            row[2 + half]  = hy;
            row[4 + half]  = hz;
            const float* e = env + (b * 512 + m) * 3;
            row[6 + half]  = e[0] * sw;
            row[8 + half]  = e[1] * sw;
            row[10 + half] = e[2] * sw;
        }
    }
}

// ---------------- per-pixel normal prep ----------------
__device__ __forceinline__ void load_normal(const float* __restrict__ nptr,
                                            float& nx, float& ny, float& nz) {
    float c0 = nptr[0], c1 = nptr[1], c2 = nptr[2];
    nx = (c2 - 0.5f) * 2.0f;
    ny = (c1 - 0.5f) * 2.0f;
    nz = (c0 - 0.5f) * 2.0f;
    float nn = sqrtf(nx * nx + ny * ny + nz * nz);
    float iv = 1.0f / fmaxf(nn, 1e-12f);
    nx *= iv; ny *= iv; nz *= iv;
}

// ---------------- kernel 1: global max, warp-level work stealing ----------------
// Units: 8192 units of 64 px (2 px/lane). Plus the analytic eh=0 light.
__global__ void __launch_bounds__(256, 2) k_max(const float* __restrict__ normal) {
    __shared__ __align__(16) float4 ta[240];
    __shared__ __align__(16) u64   tz[240];
    __shared__ float wm[8];
    for (int i = threadIdx.x; i < 240; i += 256) {
        ta[i] = ((const float4*)g_mtab_a)[i];
        tz[i] = ((const u64*)g_mtab_z)[i];
    }
    __syncthreads();

    int lane = threadIdx.x & 31;
    const float R2I = 0.70710678118654752f;   // 1/sqrt(2): eh=0 light h=(0,1,1)/sqrt2
    float mx = 0.0f;

    for (;;) {
        u32 u;
        if (lane == 0) u = atomicAdd(&g_ctr_max, 1u);
        u = __shfl_sync(0xffffffffu, u, 0);
        if (u >= 8192u) break;

        int p0 = (int)u * 64 + lane;
        int p1 = p0 + 32;
        float ax, ay, az, bx, by, bz;
        load_normal(normal + p0 * 3, ax, ay, az);
        load_normal(normal + p1 * 3, bx, by, bz);
        // analytic eh=0 light (covers all 32 duplicates)
        mx = fmaxf(mx, fmaxf((ay + az) * R2I, (by + bz) * R2I));

        u64 ax2 = dup2(ax), ay2 = dup2(ay), az2 = dup2(az);
        u64 bx2 = dup2(bx), by2 = dup2(by), bz2 = dup2(bz);
        u64 ma = 0ull, mb = 0ull;
        #pragma unroll 8
        for (int j = 0; j < 240; ++j) {
            float4 q = ta[j];
            u64 hx01 = pk2(q.x, q.y), hy01 = pk2(q.z, q.w), hz01 = tz[j];
            u64 sa = fma2_(ax2, hx01, fma2_(ay2, hy01, mul2_(az2, hz01)));
            u64 sb = fma2_(bx2, hx01, fma2_(by2, hy01, mul2_(bz2, hz01)));
            ma = max2_s32(ma, sa);
            mb = max2_s32(mb, sb);
        }
        u64 mm = max2_s32(ma, mb);
        float l0, h0; unpk2(mm, l0, h0);
        mx = fmaxf(mx, fmaxf(l0, h0));
    }

    #pragma unroll
    for (int o = 16; o; o >>= 1) mx = fmaxf(mx, __shfl_xor_sync(0xffffffffu, mx, o));
    if (lane == 0) wm[threadIdx.x >> 5] = mx;
    __syncthreads();
    if (threadIdx.x == 0) {
        float m2 = wm[0];
        #pragma unroll
        for (int i = 1; i < 8; ++i) m2 = fmaxf(m2, wm[i]);
        atomicMax(&g_maxbits, __float_as_uint(m2));  // nonneg float bits monotone as uint
    }
}

// ---------------- kernel 2: fused shade, warp-level work stealing ----------------
// Units: 16384 units of 32 px (1 px/lane); unit u: batch = u>>13, px = (u&8191)*32+lane.
// Both batch tables resident in smem (23KB) so any unit is served without reload.
__global__ void __launch_bounds__(256, 2) k_shade(const float* __restrict__ normal,
                                                  float* __restrict__ out) {
    __shared__ __align__(16) float4 tab[2 * 720];
    for (int i = threadIdx.x; i < 2 * 720; i += 256)
        tab[i] = ((const float4*)g_stab)[i];
    __syncthreads();

    int lane = threadIdx.x & 31;
    float gm = __uint_as_float(g_maxbits);
    float sc = 1.0f / gm;                        // fold 1/max into the normal

    for (;;) {
        u32 u;
        if (lane == 0) u = atomicAdd(&g_ctr_shade, 1u);
        u = __shfl_sync(0xffffffffu, u, 0);
        if (u >= 16384u) break;

        int b = (int)(u >> 13);
        int i = (int)(u & 8191u) * 32 + lane;    // pixel within batch
        const float4* T = &tab[b * 720];

        float nx, ny, nz;
        load_normal(normal + (b * HW + i) * 3, nx, ny, nz);
        u64 nx2 = dup2(nx * sc), ny2 = dup2(ny * sc), nz2 = dup2(nz * sc);

        u64 Ar = 0ull, Ag = 0ull, Ab = 0ull;
        #pragma unroll 4
        for (int j = 0; j < 240; ++j) {
            float4 q0 = T[j * 3 + 0];
            float4 q1 = T[j * 3 + 1];
            float4 q2 = T[j * 3 + 2];
            u64 hx = pk2(q0.x, q0.y), hy = pk2(q0.z, q0.w), hz = pk2(q1.x, q1.y);
            u64 wr = pk2(q1.z, q1.w), wg = pk2(q2.x, q2.y), wb = pk2(q2.z, q2.w);

            u64 s = fma2_(nx2, hx, fma2_(ny2, hy, mul2_(nz2, hz)));
            u64 c = relu2(s);
            c = mul2_(c, c);                 // ^2
            c = mul2_(c, c);                 // ^4
            c = mul2_(c, c);                 // ^8
            c = mul2_(c, c);                 // ^16
            c = mul2_(c, c);                 // ^32
            c = mul2_(c, c);                 // ^64
            Ar = fma2_(c, wr, Ar);
            Ag = fma2_(c, wg, Ag);
            Ab = fma2_(c, wb, Ab);
        }

        float r0, r1, g0, g1, b0, b1;
        unpk2(Ar, r0, r1); unpk2(Ag, g0, g1); unpk2(Ab, b0, b1);
        int ob = b * 3 * HW + i;
        out[ob]          = r0 + r1;
        out[ob + HW]     = g0 + g1;
        out[ob + 2 * HW] = b0 + b1;
    }
}

// ---------------- launch ----------------
extern "C" void kernel_launch(void* const* d_in, const int* in_sizes, int n_in,
                              void* d_out, int out_size) {
    const float* env    = (const float*)d_in[0];
    const float* normal = (const float*)d_in[1];
    if (n_in >= 2 && in_sizes[0] > in_sizes[1]) {
        env    = (const float*)d_in[1];
        normal = (const float*)d_in[0];
    }
    k_setup<<<1, 512>>>(env);
    k_max<<<296, 256>>>(normal);
    k_shade<<<296, 256>>>(normal, (float*)d_out);
}

// round 8
// speedup vs baseline: 1.1133x; 1.1133x over previous
#include <cuda_runtime.h>

typedef unsigned long long u64;
typedef unsigned int u32;

#define HW (512*512)

// ---------------- device scratch ----------------
// Shade table: per batch b (2), per m-pair mp (240; eh>=1 lights only), 16 floats (64B):
//   [hx0,hx1, hy0,hy1, hz0,hz1, wr0,wr1, wg0,wg1, wb0,wb1, pad x4]
// w = env * sin(phi) / 60.  The 32 eh=0 lights have w == 0 exactly -> dropped from shade.
__device__ __align__(16) float g_table[2 * 240 * 16];
__device__ u32 g_maxbits;

// ---------------- packed f32x2 helpers ----------------
__device__ __forceinline__ u64 pk2(float lo, float hi) {
    u64 r;
    asm("mov.b64 %0, {%1, %2};" : "=l"(r) : "r"(__float_as_uint(lo)), "r"(__float_as_uint(hi)));
    return r;
}
__device__ __forceinline__ void unpk2(u64 v, float& lo, float& hi) {
    u32 a, b;
    asm("mov.b64 {%0, %1}, %2;" : "=r"(a), "=r"(b) : "l"(v));
    lo = __uint_as_float(a); hi = __uint_as_float(b);
}
__device__ __forceinline__ u64 dup2(float x) { return pk2(x, x); }
__device__ __forceinline__ u64 fma2_(u64 a, u64 b, u64 c) {
    u64 d; asm("fma.rn.f32x2 %0, %1, %2, %3;" : "=l"(d) : "l"(a), "l"(b), "l"(c)); return d;
}
__device__ __forceinline__ u64 mul2_(u64 a, u64 b) {
    u64 d; asm("mul.rn.f32x2 %0, %1, %2;" : "=l"(d) : "l"(a), "l"(b)); return d;
}
// packed relu: bits(relu(x)) == max_s32(bits(x), 0)
__device__ __forceinline__ u64 relu2(u64 s) {
    u32 lo, hi;
    asm("mov.b64 {%0,%1}, %2;" : "=r"(lo), "=r"(hi) : "l"(s));
    asm("max.s32 %0, %0, 0;" : "+r"(lo));
    asm("max.s32 %0, %0, 0;" : "+r"(hi));
    u64 r;
    asm("mov.b64 %0, {%1,%2};" : "=l"(r) : "r"(lo), "r"(hi));
    return r;
}
// packed running-max (halves of m >= 0, so s32 max == float max)
__device__ __forceinline__ u64 max2_s32(u64 m, u64 s) {
    u32 ml, mh, sl, sh;
    asm("mov.b64 {%0,%1}, %2;" : "=r"(ml), "=r"(mh) : "l"(m));
    asm("mov.b64 {%0,%1}, %2;" : "=r"(sl), "=r"(sh) : "l"(s));
    asm("max.s32 %0, %0, %1;" : "+r"(ml) : "r"(sl));
    asm("max.s32 %0, %0, %1;" : "+r"(mh) : "r"(sh));
    u64 r;
    asm("mov.b64 %0, {%1,%2};" : "=l"(r) : "r"(ml), "r"(mh));
    return r;
}

// ---------------- kernel 0: constants + table + scratch reset ----------------
__global__ void k_setup(const float* __restrict__ env) {
    int m = threadIdx.x;              // 0..511
    if (m == 0) g_maxbits = 0u;

    int eh = m >> 5, ew = m & 31;
    const float PI_F = 3.14159274101257324e+00f;
    float phi = ((float)eh * (1.0f / 16.0f)) * PI_F;
    float th  = (((float)ew * (1.0f / 32.0f)) * 2.0f) * PI_F;

    float sp = sinf(phi), cp = cosf(phi);
    float st = sinf(th),  ct = cosf(th);

    // l = (st*sp, cp, -ct*sp); v = (0,0,1); h = normalize(v + l)
    float hx = st * sp;
    float hy = cp;
    float hz = 1.0f - ct * sp;
    float nrm = sqrtf(hx * hx + hy * hy + hz * hz);
    float rin = 1.0f / nrm;
    hx *= rin; hy *= rin; hz *= rin;

    if (m >= 32) {                    // eh>=1: 480 lights -> 240 pairs
        int i = m - 32, mp = i >> 1, half = i & 1;
        const float SC = (float)(1.0 / 60.0);
        float sw = sp * SC;

        #pragma unroll
        for (int b = 0; b < 2; ++b) {
            float* row = g_table + (b * 240 + mp) * 16;
            row[0 + half]  = hx;
            row[2 + half]  = hy;
            row[4 + half]  = hz;
            const float* e = env + (b * 512 + m) * 3;
            row[6 + half]  = e[0] * sw;
            row[8 + half]  = e[1] * sw;
            row[10 + half] = e[2] * sw;
            if (half == 0) { row[12] = 0.f; row[13] = 0.f; row[14] = 0.f; row[15] = 0.f; }
        }
    }
}

// ---------------- per-pixel normal prep ----------------
__device__ __forceinline__ void load_normal(const float* __restrict__ nptr,
                                            float& nx, float& ny, float& nz) {
    float c0 = nptr[0], c1 = nptr[1], c2 = nptr[2];
    nx = (c2 - 0.5f) * 2.0f;
    ny = (c1 - 0.5f) * 2.0f;
    nz = (c0 - 0.5f) * 2.0f;
    float nn = sqrtf(nx * nx + ny * ny + nz * nz);
    float iv = 1.0f / fmaxf(nn, 1e-12f);
    nx *= iv; ny *= iv; nz *= iv;
}

// ---------------- kernel 1: global max of relu(dot), 2 pixels/thread ----------------
// 240 table pairs + one analytic light for the 32 identical eh=0 dirs: h=(0,1,1)/sqrt2.
__global__ void __launch_bounds__(256, 2) k_max(const float* __restrict__ normal) {
    __shared__ float4 tab[960];   // 240 pairs * 4 float4 (batch-0; h is batch-independent)
    __shared__ float wm[8];
    const float4* gt = (const float4*)g_table;
    for (int i = threadIdx.x; i < 960; i += 256) tab[i] = gt[i];
    __syncthreads();

    int p0 = blockIdx.x * 256 + threadIdx.x;     // 0..262143
    int p1 = p0 + 262144;
    float ax, ay, az, bx, by, bz;
    load_normal(normal + p0 * 3, ax, ay, az);
    load_normal(normal + p1 * 3, bx, by, bz);
    u64 ax2 = dup2(ax), ay2 = dup2(ay), az2 = dup2(az);
    u64 bx2 = dup2(bx), by2 = dup2(by), bz2 = dup2(bz);

    const float R2I = 0.70710678118654752f;      // 1/sqrt(2)
    float mx = fmaxf(fmaxf((ay + az) * R2I, (by + bz) * R2I), 0.0f);

    u64 ma = 0ull, mb = 0ull;   // packed running max, halves start at +0
    #pragma unroll 8
    for (int mp = 0; mp < 240; ++mp) {
        float4 q0 = tab[mp * 4 + 0];  // hx0,hx1,hy0,hy1
        float4 q1 = tab[mp * 4 + 1];  // hz0,hz1,wr0,wr1
        u64 hx01 = pk2(q0.x, q0.y), hy01 = pk2(q0.z, q0.w), hz01 = pk2(q1.x, q1.y);
        u64 sa = fma2_(ax2, hx01, fma2_(ay2, hy01, mul2_(az2, hz01)));
        u64 sb = fma2_(bx2, hx01, fma2_(by2, hy01, mul2_(bz2, hz01)));
        ma = max2_s32(ma, sa);
        mb = max2_s32(mb, sb);
    }

    float l0, h0, l1, h1;
    unpk2(ma, l0, h0); unpk2(mb, l1, h1);
    mx = fmaxf(mx, fmaxf(fmaxf(l0, h0), fmaxf(l1, h1)));

    #pragma unroll
    for (int o = 16; o; o >>= 1) mx = fmaxf(mx, __shfl_xor_sync(0xffffffffu, mx, o));
    if ((threadIdx.x & 31) == 0) wm[threadIdx.x >> 5] = mx;
    __syncthreads();
    if (threadIdx.x == 0) {
        float m2 = wm[0];
        #pragma unroll
        for (int i = 1; i < 8; ++i) m2 = fmaxf(m2, wm[i]);
        atomicMax(&g_maxbits, __float_as_uint(m2));  // nonneg bits monotone as uint
    }
}

// ---------------- kernel 2: fused shade, 2 pixels/thread, 240 pairs ----------------
__global__ void __launch_bounds__(256, 2) k_shade(const float* __restrict__ normal,
                                                  float* __restrict__ out) {
    __shared__ float4 tab[960];   // 15KB table for this batch
    int b = blockIdx.y;
    const float4* gt = (const float4*)g_table + b * 960;
    for (int i = threadIdx.x; i < 960; i += 256) tab[i] = gt[i];
    __syncthreads();

    int i0 = blockIdx.x * 256 + threadIdx.x;     // 0..131071 within batch
    int i1 = i0 + 131072;

    float gm = __uint_as_float(g_maxbits);
    float sc = 1.0f / gm;                        // fold 1/max into the normal

    float ax, ay, az, bx, by, bz;
    load_normal(normal + (b * HW + i0) * 3, ax, ay, az);
    load_normal(normal + (b * HW + i1) * 3, bx, by, bz);
    u64 ax2 = dup2(ax * sc), ay2 = dup2(ay * sc), az2 = dup2(az * sc);
    u64 bx2 = dup2(bx * sc), by2 = dup2(by * sc), bz2 = dup2(bz * sc);

    u64 ar0 = 0ull, ag0 = 0ull, ab0 = 0ull;
    u64 ar1 = 0ull, ag1 = 0ull, ab1 = 0ull;

    #pragma unroll 4
    for (int mp = 0; mp < 240; ++mp) {
        float4 q0 = tab[mp * 4 + 0];
        float4 q1 = tab[mp * 4 + 1];
        float4 q2 = tab[mp * 4 + 2];
        u64 hx01 = pk2(q0.x, q0.y), hy01 = pk2(q0.z, q0.w), hz01 = pk2(q1.x, q1.y);
        u64 wr01 = pk2(q1.z, q1.w), wg01 = pk2(q2.x, q2.y), wb01 = pk2(q2.z, q2.w);

        // pixel 0
        u64 sa = fma2_(ax2, hx01, fma2_(ay2, hy01, mul2_(az2, hz01)));
        u64 ua = relu2(sa);
        u64 ca = mul2_(ua, ua);          // ^2
        ca = mul2_(ca, ca);              // ^4
        ca = mul2_(ca, ca);              // ^8
        ca = mul2_(ca, ca);              // ^16
        ca = mul2_(ca, ca);              // ^32
        ca = mul2_(ca, ca);              // ^64
        ar0 = fma2_(ca, wr01, ar0);
        ag0 = fma2_(ca, wg01, ag0);
        ab0 = fma2_(ca, wb01, ab0);

        // pixel 1
        u64 sb = fma2_(bx2, hx01, fma2_(by2, hy01, mul2_(bz2, hz01)));
        u64 ub = relu2(sb);
        u64 cb = mul2_(ub, ub);
        cb = mul2_(cb, cb);
        cb = mul2_(cb, cb);
        cb = mul2_(cb, cb);
        cb = mul2_(cb, cb);
        cb = mul2_(cb, cb);
        ar1 = fma2_(cb, wr01, ar1);
        ag1 = fma2_(cb, wg01, ag1);
        ab1 = fma2_(cb, wb01, ab1);
    }

    float r0, r1, g0, g1, bb0, bb1;
    int ob = b * 3 * HW;
    unpk2(ar0, r0, r1); unpk2(ag0, g0, g1); unpk2(ab0, bb0, bb1);
    out[ob + i0]          = r0 + r1;
    out[ob + HW + i0]     = g0 + g1;
    out[ob + 2 * HW + i0] = bb0 + bb1;
    unpk2(ar1, r0, r1); unpk2(ag1, g0, g1); unpk2(ab1, bb0, bb1);
    out[ob + i1]          = r0 + r1;
    out[ob + HW + i1]     = g0 + g1;
    out[ob + 2 * HW + i1] = bb0 + bb1;
}

// ---------------- launch ----------------
extern "C" void kernel_launch(void* const* d_in, const int* in_sizes, int n_in,
                              void* d_out, int out_size) {
    const float* env    = (const float*)d_in[0];
    const float* normal = (const float*)d_in[1];
    if (n_in >= 2 && in_sizes[0] > in_sizes[1]) {
        env    = (const float*)d_in[1];
        normal = (const float*)d_in[0];
    }
    k_setup<<<1, 512>>>(env);
    k_max<<<1024, 256>>>(normal);
    k_shade<<<dim3(512, 2), 256>>>(normal, (float*)d_out);
}